// round 15
// baseline (speedup 1.0000x reference)
#include <cuda_runtime.h>
#include <cuda_fp16.h>
#include <cstdint>

// GAPooling: out[b,n,c] = (1/K) * sum_k x[b, idx[b,n,k], c]
// x [16,4096,64] fp32, idx [16,4096,32] int32, out fp32.
//
// Converged design (14 rounds of ncu-driven iteration):
// Stage 1: x -> fp16 table (8 MB, L2-resident). Row = 128 B = one L1 line.
//          x read via __ldg (one-shot stream; don't churn L2 table lines).
// Stage 2: warp per point; 8x LDG.128 gathers (4 whole rows each -- the
//          wavefront-optimal shape: 1 line per gathered row, max bytes per
//          LDG instruction), per-lane idx loads (the warp's whole index
//          stream lives in one 128 B line; zero SHFL on the LSU/MIO path),
//          hadd2 chains of 4 with fp32 spill, butterfly reduce over the 4
//          row-slots, coalesced fp32 store. Carveout 0 -> max L1D.
// Measured equilibrium: stage2 ~21.5 us (L1tex per-line gather floor ~14 us
// + L2-hit latency exposure); chunk-pipelining, evict policies, persistent
// batch-affinity, narrow/wide LDG reshaping, and SW prefetch all regressed
// or were neutral.

static constexpr int B = 16;
static constexpr int N = 4096;
static constexpr int C = 64;
static constexpr int K = 32;

__device__ __half g_xh[(size_t)B * N * C];   // 8 MB fp16 table

__global__ __launch_bounds__(256) void cvt_kernel(const float* __restrict__ x)
{
    const int t = blockIdx.x * blockDim.x + threadIdx.x;   // B*N*C/8 threads
    const float4* __restrict__ xi = reinterpret_cast<const float4*>(x);
    const float4 a = __ldg(xi + 2 * t);
    const float4 b = __ldg(xi + 2 * t + 1);
    __half2 h[4];
    h[0] = __floats2half2_rn(a.x, a.y);
    h[1] = __floats2half2_rn(a.z, a.w);
    h[2] = __floats2half2_rn(b.x, b.y);
    h[3] = __floats2half2_rn(b.z, b.w);
    reinterpret_cast<uint4*>(g_xh)[t] = *reinterpret_cast<uint4*>(h);
}

__global__ __launch_bounds__(256) void gap_f16_kernel(
    const int* __restrict__ idx,
    float* __restrict__ out)
{
    const int warp_global = (blockIdx.x * blockDim.x + threadIdx.x) >> 5;
    const int lane = threadIdx.x & 31;

    const int b  = warp_global >> 12;          // N = 4096 = 2^12
    const int r  = lane >> 3;                  // 0..3  (row slot within LDG)
    const int cq = lane & 7;                   // 0..7  (16 B channel chunk)

    // This lane's index stream: positions r, r+4, ..., r+28. One 128 B line.
    const int* __restrict__ iw = idx + (size_t)warp_global * K + r;

    const __half* __restrict__ xb = g_xh + (size_t)b * N * C + cq * 8;

    float acc[8];
    #pragma unroll
    for (int c = 0; c < 8; c++) acc[c] = 0.f;

    #pragma unroll
    for (int blk = 0; blk < 2; blk++) {
        __half2 hacc[4];
        #pragma unroll
        for (int q = 0; q < 4; q++) hacc[q] = __half2half2(__ushort_as_half(0));

        #pragma unroll
        for (int i = 0; i < 4; i++) {
            const int j = __ldg(iw + (blk * 4 + i) * 4);   // slot r, quad i
            const float4 raw = *reinterpret_cast<const float4*>(
                xb + (size_t)j * C);                        // 16 B = 8 halves
            const __half2* h2 = reinterpret_cast<const __half2*>(&raw);
            #pragma unroll
            for (int q = 0; q < 4; q++)
                hacc[q] = __hadd2(hacc[q], h2[q]);
        }

        #pragma unroll
        for (int q = 0; q < 4; q++) {
            const float2 f = __half22float2(hacc[q]);
            acc[2 * q]     += f.x;
            acc[2 * q + 1] += f.y;
        }
    }

    // reduce the 4 r-groups (lane bits 3,4) in fp32
    #pragma unroll
    for (int c = 0; c < 8; c++) {
        acc[c] += __shfl_xor_sync(0xffffffffu, acc[c], 8);
        acc[c] += __shfl_xor_sync(0xffffffffu, acc[c], 16);
    }

    if (r == 0) {
        const float inv_k = 1.0f / (float)K;
        float4 o0, o1;
        o0.x = acc[0] * inv_k; o0.y = acc[1] * inv_k;
        o0.z = acc[2] * inv_k; o0.w = acc[3] * inv_k;
        o1.x = acc[4] * inv_k; o1.y = acc[5] * inv_k;
        o1.z = acc[6] * inv_k; o1.w = acc[7] * inv_k;
        float4* op = reinterpret_cast<float4*>(
            out + (size_t)warp_global * C + cq * 8);
        op[0] = o0;
        op[1] = o1;
    }
}

extern "C" void kernel_launch(void* const* d_in, const int* in_sizes, int n_in,
                              void* d_out, int out_size)
{
    // Select inputs by element count (ordering-proof):
    //   x:   B*N*C = 4,194,304 ; idx: B*N*K = 2,097,152
    const float* x = nullptr;
    const int* idx = nullptr;
    for (int i = 0; i < n_in; i++) {
        if (in_sizes[i] == B * N * C) x = (const float*)d_in[i];
        else if (in_sizes[i] == B * N * K) idx = (const int*)d_in[i];
    }
    if (!x) x = (const float*)d_in[0];
    if (!idx) idx = (const int*)d_in[1];
    float* out = (float*)d_out;

    // One-time: request 0% smem carveout -> maximum L1D for the gather.
    static bool attr_done = false;
    if (!attr_done) {
        cudaFuncSetAttribute(gap_f16_kernel,
                             cudaFuncAttributePreferredSharedMemoryCarveout, 0);
        attr_done = true;
    }

    // Stage 1: fp32 -> fp16 table
    const int cvt_threads = (B * N * C) / 8;               // 524288
    cvt_kernel<<<cvt_threads / 256, 256>>>(x);

    // Stage 2: gather-mean, one warp per point (exact grid, no tail)
    const int total_warps = B * N;                          // 65536
    gap_f16_kernel<<<(total_warps * 32) / 256, 256>>>(idx, out);
}

// round 16
// speedup vs baseline: 1.0102x; 1.0102x over previous
#include <cuda_runtime.h>
#include <cuda_fp16.h>
#include <cstdint>

// GAPooling: out[b,n,c] = (1/K) * sum_k x[b, idx[b,n,k], c]
// x [16,4096,64] fp32, idx [16,4096,32] int32, out fp32.
//
// Converged gather design (rounds 2-15) + NEW: PDL overlap.
// Stage 1 (cvt): x -> fp16 table (8 MB). Row = 128 B = one L1 line.
//   Triggers griddepcontrol.launch_dependents AFTER its table stores.
// Stage 2 (gap): launched with programmaticStreamSerialization -> starts
//   while cvt drains. Preamble (idx loads, one 128 B line per warp; no
//   table dependency) runs concurrently with cvt's tail; griddepcontrol.wait
//   gates only the first table gather (PDL guarantees store visibility).
//   Then: 8x LDG.128 gathers (4 whole rows each, wavefront-optimal),
//   hadd2 chains of 4 with fp32 spill, butterfly reduce, coalesced store.

static constexpr int B = 16;
static constexpr int N = 4096;
static constexpr int C = 64;
static constexpr int K = 32;

__device__ __half g_xh[(size_t)B * N * C];   // 8 MB fp16 table

__global__ __launch_bounds__(256) void cvt_kernel(const float* __restrict__ x)
{
    const int t = blockIdx.x * blockDim.x + threadIdx.x;   // B*N*C/8 threads
    const float4* __restrict__ xi = reinterpret_cast<const float4*>(x);
    const float4 a = __ldg(xi + 2 * t);
    const float4 b = __ldg(xi + 2 * t + 1);
    __half2 h[4];
    h[0] = __floats2half2_rn(a.x, a.y);
    h[1] = __floats2half2_rn(a.z, a.w);
    h[2] = __floats2half2_rn(b.x, b.y);
    h[3] = __floats2half2_rn(b.z, b.w);
    reinterpret_cast<uint4*>(g_xh)[t] = *reinterpret_cast<uint4*>(h);
    // Allow dependents to launch; writes above are visible to any thread
    // that executes griddepcontrol.wait (PDL memory-ordering guarantee).
    asm volatile("griddepcontrol.launch_dependents;" ::: "memory");
}

__global__ __launch_bounds__(256) void gap_f16_kernel(
    const int* __restrict__ idx,
    float* __restrict__ out)
{
    const int warp_global = (blockIdx.x * blockDim.x + threadIdx.x) >> 5;
    const int lane = threadIdx.x & 31;

    const int b  = warp_global >> 12;          // N = 4096 = 2^12
    const int r  = lane >> 3;                  // 0..3  (row slot within LDG)
    const int cq = lane & 7;                   // 0..7  (16 B channel chunk)

    // ---- PDL preamble: no table dependency ----
    // This lane's index stream: positions r, r+4, ..., r+28. One 128 B line.
    const int* __restrict__ iw = idx + (size_t)warp_global * K + r;
    int jv[8];
    #pragma unroll
    for (int i = 0; i < 8; i++)
        jv[i] = __ldg(iw + i * 4);

    // Block until cvt's table stores are visible.
    asm volatile("griddepcontrol.wait;" ::: "memory");

    const __half* __restrict__ xb = g_xh + (size_t)b * N * C + cq * 8;

    float acc[8];
    #pragma unroll
    for (int c = 0; c < 8; c++) acc[c] = 0.f;

    #pragma unroll
    for (int blk = 0; blk < 2; blk++) {
        __half2 hacc[4];
        #pragma unroll
        for (int q = 0; q < 4; q++) hacc[q] = __half2half2(__ushort_as_half(0));

        #pragma unroll
        for (int i = 0; i < 4; i++) {
            const float4 raw = *reinterpret_cast<const float4*>(
                xb + (size_t)jv[blk * 4 + i] * C);          // 16 B = 8 halves
            const __half2* h2 = reinterpret_cast<const __half2*>(&raw);
            #pragma unroll
            for (int q = 0; q < 4; q++)
                hacc[q] = __hadd2(hacc[q], h2[q]);
        }

        #pragma unroll
        for (int q = 0; q < 4; q++) {
            const float2 f = __half22float2(hacc[q]);
            acc[2 * q]     += f.x;
            acc[2 * q + 1] += f.y;
        }
    }

    // reduce the 4 r-groups (lane bits 3,4) in fp32
    #pragma unroll
    for (int c = 0; c < 8; c++) {
        acc[c] += __shfl_xor_sync(0xffffffffu, acc[c], 8);
        acc[c] += __shfl_xor_sync(0xffffffffu, acc[c], 16);
    }

    if (r == 0) {
        const float inv_k = 1.0f / (float)K;
        float4 o0, o1;
        o0.x = acc[0] * inv_k; o0.y = acc[1] * inv_k;
        o0.z = acc[2] * inv_k; o0.w = acc[3] * inv_k;
        o1.x = acc[4] * inv_k; o1.y = acc[5] * inv_k;
        o1.z = acc[6] * inv_k; o1.w = acc[7] * inv_k;
        float4* op = reinterpret_cast<float4*>(
            out + (size_t)warp_global * C + cq * 8);
        op[0] = o0;
        op[1] = o1;
    }
}

extern "C" void kernel_launch(void* const* d_in, const int* in_sizes, int n_in,
                              void* d_out, int out_size)
{
    // Select inputs by element count (ordering-proof):
    //   x:   B*N*C = 4,194,304 ; idx: B*N*K = 2,097,152
    const float* x = nullptr;
    const int* idx = nullptr;
    for (int i = 0; i < n_in; i++) {
        if (in_sizes[i] == B * N * C) x = (const float*)d_in[i];
        else if (in_sizes[i] == B * N * K) idx = (const int*)d_in[i];
    }
    if (!x) x = (const float*)d_in[0];
    if (!idx) idx = (const int*)d_in[1];
    float* out = (float*)d_out;

    static bool attr_done = false;
    if (!attr_done) {
        cudaFuncSetAttribute(gap_f16_kernel,
                             cudaFuncAttributePreferredSharedMemoryCarveout, 0);
        attr_done = true;
    }

    // Stage 1: fp32 -> fp16 table
    const int cvt_threads = (B * N * C) / 8;               // 524288
    cvt_kernel<<<cvt_threads / 256, 256>>>(x);

    // Stage 2: PDL launch -- overlaps its preamble (idx loads) with cvt's
    // tail; griddepcontrol.wait gates the table gathers.
    const int total_warps = B * N;                          // 65536
    cudaLaunchConfig_t cfg = {};
    cfg.gridDim  = dim3((total_warps * 32) / 256, 1, 1);
    cfg.blockDim = dim3(256, 1, 1);
    cfg.dynamicSmemBytes = 0;
    cfg.stream = 0;
    cudaLaunchAttribute attrs[1];
    attrs[0].id = cudaLaunchAttributeProgrammaticStreamSerialization;
    attrs[0].val.programmaticStreamSerializationAllowed = 1;
    cfg.attrs = attrs;
    cfg.numAttrs = 1;
    cudaLaunchKernelEx(&cfg, gap_f16_kernel, idx, out);
}

// round 17
// speedup vs baseline: 1.0273x; 1.0169x over previous
#include <cuda_runtime.h>
#include <cuda_fp16.h>
#include <cstdint>

// GAPooling: out[b,n,c] = (1/K) * sum_k x[b, idx[b,n,k], c]
// x [16,4096,64] fp32, idx [16,4096,32] int32, out fp32.
//
// Converged design (16 rounds of ncu-driven iteration):
// Stage 1 (cvt): x -> fp16 table (8 MB, L2-resident). Row = 128 B = one L1
//   line. Signals griddepcontrol.launch_dependents after its table stores.
// Stage 2 (gap): PDL launch (programmaticStreamSerialization) -- starts
//   while cvt drains; the idx-load preamble (one 128 B line per warp, no
//   table dependency) overlaps cvt's tail; griddepcontrol.wait gates the
//   first table gather. Then 8x LDG.128 gathers (4 whole rows each --
//   wavefront-optimal: 1 line per gathered row, max bytes per LDG), hadd2
//   chains of 4 with fp32 spill, butterfly reduce over the 4 row-slots,
//   coalesced fp32 store. Carveout 0 -> max L1D.
// Equilibrium: stage2 ~21.5-23 us = ~14 us L1tex per-line gather floor +
// miss/queue exposure; prefetch, eviction policy, affinity, chunk overlap,
// and LDG reshaping all measured neutral or negative.

static constexpr int B = 16;
static constexpr int N = 4096;
static constexpr int C = 64;
static constexpr int K = 32;

__device__ __half g_xh[(size_t)B * N * C];   // 8 MB fp16 table

__global__ __launch_bounds__(256) void cvt_kernel(const float* __restrict__ x)
{
    const int t = blockIdx.x * blockDim.x + threadIdx.x;   // B*N*C/8 threads
    const float4* __restrict__ xi = reinterpret_cast<const float4*>(x);
    const float4 a = __ldg(xi + 2 * t);
    const float4 b = __ldg(xi + 2 * t + 1);
    __half2 h[4];
    h[0] = __floats2half2_rn(a.x, a.y);
    h[1] = __floats2half2_rn(a.z, a.w);
    h[2] = __floats2half2_rn(b.x, b.y);
    h[3] = __floats2half2_rn(b.z, b.w);
    reinterpret_cast<uint4*>(g_xh)[t] = *reinterpret_cast<uint4*>(h);
    // Allow dependents to launch; writes above are visible to any thread
    // that executes griddepcontrol.wait (PDL memory-ordering guarantee).
    asm volatile("griddepcontrol.launch_dependents;" ::: "memory");
}

__global__ __launch_bounds__(256) void gap_f16_kernel(
    const int* __restrict__ idx,
    float* __restrict__ out)
{
    const int warp_global = (blockIdx.x * blockDim.x + threadIdx.x) >> 5;
    const int lane = threadIdx.x & 31;

    const int b  = warp_global >> 12;          // N = 4096 = 2^12
    const int r  = lane >> 3;                  // 0..3  (row slot within LDG)
    const int cq = lane & 7;                   // 0..7  (16 B channel chunk)

    // ---- PDL preamble: no table dependency ----
    // This lane's index stream: positions r, r+4, ..., r+28. One 128 B line.
    const int* __restrict__ iw = idx + (size_t)warp_global * K + r;
    int jv[8];
    #pragma unroll
    for (int i = 0; i < 8; i++)
        jv[i] = __ldg(iw + i * 4);

    // Block until cvt's table stores are visible.
    asm volatile("griddepcontrol.wait;" ::: "memory");

    const __half* __restrict__ xb = g_xh + (size_t)b * N * C + cq * 8;

    float acc[8];
    #pragma unroll
    for (int c = 0; c < 8; c++) acc[c] = 0.f;

    #pragma unroll
    for (int blk = 0; blk < 2; blk++) {
        __half2 hacc[4];
        #pragma unroll
        for (int q = 0; q < 4; q++) hacc[q] = __half2half2(__ushort_as_half(0));

        #pragma unroll
        for (int i = 0; i < 4; i++) {
            const float4 raw = *reinterpret_cast<const float4*>(
                xb + (size_t)jv[blk * 4 + i] * C);          // 16 B = 8 halves
            const __half2* h2 = reinterpret_cast<const __half2*>(&raw);
            #pragma unroll
            for (int q = 0; q < 4; q++)
                hacc[q] = __hadd2(hacc[q], h2[q]);
        }

        #pragma unroll
        for (int q = 0; q < 4; q++) {
            const float2 f = __half22float2(hacc[q]);
            acc[2 * q]     += f.x;
            acc[2 * q + 1] += f.y;
        }
    }

    // reduce the 4 r-groups (lane bits 3,4) in fp32
    #pragma unroll
    for (int c = 0; c < 8; c++) {
        acc[c] += __shfl_xor_sync(0xffffffffu, acc[c], 8);
        acc[c] += __shfl_xor_sync(0xffffffffu, acc[c], 16);
    }

    if (r == 0) {
        const float inv_k = 1.0f / (float)K;
        float4 o0, o1;
        o0.x = acc[0] * inv_k; o0.y = acc[1] * inv_k;
        o0.z = acc[2] * inv_k; o0.w = acc[3] * inv_k;
        o1.x = acc[4] * inv_k; o1.y = acc[5] * inv_k;
        o1.z = acc[6] * inv_k; o1.w = acc[7] * inv_k;
        float4* op = reinterpret_cast<float4*>(
            out + (size_t)warp_global * C + cq * 8);
        op[0] = o0;
        op[1] = o1;
    }
}

extern "C" void kernel_launch(void* const* d_in, const int* in_sizes, int n_in,
                              void* d_out, int out_size)
{
    // Select inputs by element count (ordering-proof):
    //   x:   B*N*C = 4,194,304 ; idx: B*N*K = 2,097,152
    const float* x = nullptr;
    const int* idx = nullptr;
    for (int i = 0; i < n_in; i++) {
        if (in_sizes[i] == B * N * C) x = (const float*)d_in[i];
        else if (in_sizes[i] == B * N * K) idx = (const int*)d_in[i];
    }
    if (!x) x = (const float*)d_in[0];
    if (!idx) idx = (const int*)d_in[1];
    float* out = (float*)d_out;

    static bool attr_done = false;
    if (!attr_done) {
        cudaFuncSetAttribute(gap_f16_kernel,
                             cudaFuncAttributePreferredSharedMemoryCarveout, 0);
        attr_done = true;
    }

    // Stage 1: fp32 -> fp16 table
    const int cvt_threads = (B * N * C) / 8;               // 524288
    cvt_kernel<<<cvt_threads / 256, 256>>>(x);

    // Stage 2: PDL launch -- overlaps its preamble (idx loads) with cvt's
    // tail; griddepcontrol.wait gates the table gathers.
    const int total_warps = B * N;                          // 65536
    cudaLaunchConfig_t cfg = {};
    cfg.gridDim  = dim3((total_warps * 32) / 256, 1, 1);
    cfg.blockDim = dim3(256, 1, 1);
    cfg.dynamicSmemBytes = 0;
    cfg.stream = 0;
    cudaLaunchAttribute attrs[1];
    attrs[0].id = cudaLaunchAttributeProgrammaticStreamSerialization;
    attrs[0].val.programmaticStreamSerializationAllowed = 1;
    cfg.attrs = attrs;
    cfg.numAttrs = 1;
    cudaLaunchKernelEx(&cfg, gap_f16_kernel, idx, out);
}